// round 3
// baseline (speedup 1.0000x reference)
#include <cuda_runtime.h>
#include <cstdint>

// ---------------------------------------------------------------------------
// ParticleExplorer: B particles, N serial steps.
// Per step (exact-math equivalent of the reference's double Rodrigues+renorm):
//   E <- E * Rz(pa_t) * Ry(na_t)      (E columns = e0,e1,e2)
//   x <- x + sp_t * e0
// Output layout (concatenated float32):
//   ts[N] | X[B][N][3] | states[B][N] (zeros) | speeds[B][N] | pa[B][N] | na[B][N]
// ---------------------------------------------------------------------------

#define PPB 32              // particles per block (== blockDim.x)
#define TT  32              // time-tile
#define SPITCH 33           // smem pitch (conflict-free: coprime with 32)

__global__ void __launch_bounds__(PPB)
explorer_kernel(const float* __restrict__ x0,
                const float* __restrict__ e0i,
                const float* __restrict__ e1i,
                const float* __restrict__ e2i,
                const float* __restrict__ spd,
                const float* __restrict__ pan,
                const float* __restrict__ nan_,
                float* __restrict__ X,
                int B, int N)
{
    __shared__ float s_sp[TT][SPITCH];
    __shared__ float s_pa[TT][SPITCH];
    __shared__ float s_na[TT][SPITCH];
    __shared__ float s_X[3 * TT][SPITCH];

    const int lane  = threadIdx.x;
    const int pbase = blockIdx.x * PPB;
    const int p     = pbase + lane;
    const bool act  = (p < B);

    // Frame columns: a = e0, b = e1, c = e2; position (x,y,z).
    float a0=1.f,a1=0.f,a2=0.f, b0=0.f,b1=1.f,b2=0.f, c0=0.f,c1=0.f,c2=1.f;
    float x=0.f, y=0.f, z=0.f;
    if (act) {
        a0 = e0i[p*3+0]; a1 = e0i[p*3+1]; a2 = e0i[p*3+2];
        b0 = e1i[p*3+0]; b1 = e1i[p*3+1]; b2 = e1i[p*3+2];
        c0 = e2i[p*3+0]; c1 = e2i[p*3+1]; c2 = e2i[p*3+2];
        x  = x0 [p*3+0]; y  = x0 [p*3+1]; z  = x0 [p*3+2];
    }

    for (int t0 = 0; t0 < N; t0 += TT) {
        // ---- Stage inputs (coalesced): thread 'lane' reads time index t0+lane
        //      of particle pbase+k; stores transposed [t][p] for conflict-free
        //      compute reads.
        #pragma unroll
        for (int k = 0; k < PPB; k++) {
            int gp = pbase + k;
            float vs = 0.f, vp = 0.f, vn = 0.f;
            if (gp < B) {
                size_t g = (size_t)gp * N + (size_t)t0 + lane;
                vs = spd[g]; vp = pan[g]; vn = nan_[g];
            }
            s_sp[lane][k] = vs;
            s_pa[lane][k] = vp;
            s_na[lane][k] = vn;
        }
        __syncthreads();

        if (act) {
            #pragma unroll 8
            for (int tt = 0; tt < TT; tt++) {
                float s1, cc1, s2, cc2;
                __sincosf(s_pa[tt][lane], &s1, &cc1);
                __sincosf(s_na[tt][lane], &s2, &cc2);

                // M = Rz(pa)*Ry(na):
                //   col0 = ( c1c2,  s1c2, -s2 )
                //   col1 = ( -s1 ,  c1  ,  0  )
                //   col2 = ( c1s2,  s1s2,  c2 )
                float p00 = cc1 * cc2, p10 = s1 * cc2;
                float p02 = cc1 * s2,  p12 = s1 * s2;

                float na0 = fmaf(p00, a0, fmaf(p10, b0, -s2 * c0));
                float na1 = fmaf(p00, a1, fmaf(p10, b1, -s2 * c1));
                float na2 = fmaf(p00, a2, fmaf(p10, b2, -s2 * c2));

                float nb0 = fmaf(cc1, b0, -s1 * a0);
                float nb1 = fmaf(cc1, b1, -s1 * a1);
                float nb2 = fmaf(cc1, b2, -s1 * a2);

                float nc0 = fmaf(p02, a0, fmaf(p12, b0, cc2 * c0));
                float nc1 = fmaf(p02, a1, fmaf(p12, b1, cc2 * c1));
                float nc2 = fmaf(p02, a2, fmaf(p12, b2, cc2 * c2));

                a0 = na0; a1 = na1; a2 = na2;
                b0 = nb0; b1 = nb1; b2 = nb2;
                c0 = nc0; c1 = nc1; c2 = nc2;

                float s = s_sp[tt][lane];
                x = fmaf(s, a0, x);
                y = fmaf(s, a1, y);
                z = fmaf(s, a2, z);

                s_X[3*tt + 0][lane] = x;
                s_X[3*tt + 1][lane] = y;
                s_X[3*tt + 2][lane] = z;
            }

            // Cheap re-orthonormalization once per tile (keeps drift ~0).
            float inv = rsqrtf(fmaf(a0,a0, fmaf(a1,a1, a2*a2)));
            a0 *= inv; a1 *= inv; a2 *= inv;
            float d = fmaf(b0,a0, fmaf(b1,a1, b2*a2));
            b0 = fmaf(-d, a0, b0); b1 = fmaf(-d, a1, b1); b2 = fmaf(-d, a2, b2);
            inv = rsqrtf(fmaf(b0,b0, fmaf(b1,b1, b2*b2)));
            b0 *= inv; b1 *= inv; b2 *= inv;
            c0 = a1*b2 - a2*b1;
            c1 = a2*b0 - a0*b2;
            c2 = a0*b1 - a1*b0;
        }
        __syncthreads();

        // ---- Flush X tile (coalesced): each particle's 3*TT consecutive floats.
        #pragma unroll
        for (int k = 0; k < PPB; k++) {
            int gp = pbase + k;
            if (gp < B) {
                size_t base = (size_t)gp * 3 * N + (size_t)t0 * 3;
                #pragma unroll
                for (int ch = 0; ch < 3; ch++)
                    X[base + ch * 32 + lane] = s_X[ch * 32 + lane][k];
            }
        }
        // No extra sync needed: next-iter load (s_sp) and this flush (s_X)
        // touch different arrays; the post-load __syncthreads orders s_X reuse.
    }
}

__global__ void ts_kernel(float* __restrict__ ts, int N, const int* __restrict__ dtp)
{
    int i = blockIdx.x * blockDim.x + threadIdx.x;
    if (i >= N) return;
    float dtf = 1.0f;
    if (dtp != nullptr) {
        int v = dtp[0];
        if (v >= 1 && v <= 1000000) {
            dtf = (float)v;
        } else {
            float f = __int_as_float(v);
            if (f > 0.0f && f < 1.0e6f) dtf = f;
        }
    }
    ts[i] = (float)i * dtf;
}

extern "C" void kernel_launch(void* const* d_in, const int* in_sizes, int n_in,
                              void* d_out, int out_size)
{
    // Inputs per setup_inputs order:
    // 0:x0(B,3) 1:e0(B,3) 2:e1(B,3) 3:e2(B,3) 4:speeds(B,N) 5:pa(B,N) 6:na(B,N)
    // 7:T 8:dt (scalars, possibly int32 device tensors)
    const float* x0  = (const float*)d_in[0];
    const float* e0  = (const float*)d_in[1];
    const float* e1  = (const float*)d_in[2];
    const float* e2  = (const float*)d_in[3];
    const float* spd = (const float*)d_in[4];
    const float* pan = (const float*)d_in[5];
    const float* nan_ = (const float*)d_in[6];

    const int B = in_sizes[0] / 3;
    const int N = (int)((long long)in_sizes[4] / B);

    float* out    = (float*)d_out;
    float* ts     = out;
    float* X      = out + N;
    float* states = X + (size_t)3 * B * N;
    float* sp_o   = states + (size_t)B * N;
    float* pa_o   = sp_o   + (size_t)B * N;
    float* na_o   = pa_o   + (size_t)B * N;

    const size_t bn_bytes = (size_t)B * N * sizeof(float);

    // Main compute first (largest node).
    explorer_kernel<<<(B + PPB - 1) / PPB, PPB>>>(x0, e0, e1, e2, spd, pan, nan_,
                                                  X, B, N);

    // ts
    const int* dtp = (n_in > 8) ? (const int*)d_in[8] : nullptr;
    ts_kernel<<<(N + 255) / 256, 256>>>(ts, N, dtp);

    // states = zeros
    cudaMemsetAsync(states, 0, bn_bytes, 0);

    // Pass-through outputs are exact copies of inputs.
    cudaMemcpyAsync(sp_o, d_in[4], bn_bytes, cudaMemcpyDeviceToDevice, 0);
    cudaMemcpyAsync(pa_o, d_in[5], bn_bytes, cudaMemcpyDeviceToDevice, 0);
    cudaMemcpyAsync(na_o, d_in[6], bn_bytes, cudaMemcpyDeviceToDevice, 0);

    (void)out_size; (void)n_in;
}